// round 10
// baseline (speedup 1.0000x reference)
#include <cuda_runtime.h>
#include <cuda_bf16.h>
#include <mma.h>
#include <math.h>
#include <stdint.h>

using namespace nvcuda;

#define BATCH 8
#define LSEQ  1024
#define ROWS  (BATCH*LSEQ)   // 8192
#define DM    192
#define DI    384
#define DS    16
#define DTR   12
#define DBC_N (DTR + 2*DS)   // 44
#define NDEC  16384

typedef __nv_bfloat16 bf16;
typedef unsigned long long u64;

// ---------------- scratch -------------------------------------------------------
__device__ bf16  g_Apeb[ROWS*768];
__device__ bf16  g_seqb[ROWS*DM];
__device__ float g_xz  [ROWS*2*DI];
__device__ float g_uact[ROWS*DI];
__device__ bf16  g_uactb[ROWS*DI];
__device__ float g_dbc [ROWS*DBC_N];
__device__ float g_delta[ROWS*DI];
__device__ bf16  g_ygb [ROWS*DI];
__device__ bf16  g_goutb[ROWS*DM];
__device__ bf16  g_wtb [(size_t)NDEC*DM];
__device__ bf16  g_decb[(size_t)BATCH*64*512*512];   // 268 MB
__device__ bf16  g_pwb [DM*768];
__device__ bf16  g_ipwb[2*DI*DM];
__device__ bf16  g_xpwb[DBC_N*DI];
__device__ bf16  g_opwb[DM*DI];

// ---------------- helpers -------------------------------------------------------
__device__ __forceinline__ u64 pk2(float lo, float hi) {
    u64 r; asm("mov.b64 %0, {%1, %2};" : "=l"(r) : "f"(lo), "f"(hi)); return r;
}
__device__ __forceinline__ void unpk2(float& lo, float& hi, u64 v) {
    asm("mov.b64 {%0, %1}, %2;" : "=f"(lo), "=f"(hi) : "l"(v));
}
__device__ __forceinline__ void fma2(u64& acc, u64 a, u64 b) {
    asm("fma.rn.f32x2 %0, %1, %2, %0;" : "+l"(acc) : "l"(a), "l"(b));
}
__device__ __forceinline__ uint32_t smem_u32(const void* p) {
    uint32_t a;
    asm("{ .reg .u64 t; cvta.to.shared.u64 t, %1; cvt.u32.u64 %0, t; }" : "=r"(a) : "l"(p));
    return a;
}
__device__ __forceinline__ float ex2_approx(float x) {
    float r; asm("ex2.approx.f32 %0, %1;" : "=f"(r) : "f"(x)); return r;
}

// ---------------- merged weight converts ----------------------------------------
#define W0 (DM*768)
#define W1 (W0 + 2*DI*DM)
#define W2 (W1 + DBC_N*DI)
#define W3 (W2 + DM*DI)
__global__ void cvt_weights_kernel(const float* __restrict__ pw, const float* __restrict__ ipw,
                                   const float* __restrict__ xpw, const float* __restrict__ opw) {
    int i = blockIdx.x * 256 + threadIdx.x;
    if (i >= W3) return;
    if (i < W0)      g_pwb [i]      = __float2bfloat16(pw [i]);
    else if (i < W1) g_ipwb[i - W0] = __float2bfloat16(ipw[i - W0]);
    else if (i < W2) g_xpwb[i - W1] = __float2bfloat16(xpw[i - W1]);
    else             g_opwb[i - W2] = __float2bfloat16(opw[i - W2]);
}

__global__ void transpose_w_kernel(const float* __restrict__ W) {
    __shared__ float t[32][33];
    int bn = blockIdx.x * 32, bk = blockIdx.y * 32;
    int tx = threadIdx.x & 31, ty = threadIdx.x >> 5;
#pragma unroll
    for (int i = ty; i < 32; i += 8) {
        int k = bk + i;
        t[i][tx] = (k < DM) ? W[(size_t)k * NDEC + bn + tx] : 0.f;
    }
    __syncthreads();
#pragma unroll
    for (int i = ty; i < 32; i += 8) {
        int k = bk + tx;
        if (k < DM)
            g_wtb[(size_t)(bn + i) * DM + k] = __float2bfloat16(t[tx][i]);
    }
}

// ---------------- im2col (writes bf16) ------------------------------------------
__global__ void im2col_kernel(const float* __restrict__ x) {
    int gid = blockIdx.x * 256 + threadIdx.x;
    if (gid >= ROWS * 768) return;
    int row = gid / 768, k = gid - row * 768;
    int c = k >> 8, rem = k & 255, p = rem >> 4, q = rem & 15;
    int b = row >> 10, hw = row & 1023, h = hw >> 5, w = hw & 31;
    g_Apeb[gid] = __float2bfloat16(x[((b * 3 + c) * 512 + h * 16 + p) * 512 + w * 16 + q]);
}

// ---------------- generic WMMA bf16 NT GEMM -------------------------------------
#define AST 72
#define CST 68
template<bool OUT_BF16>
__global__ __launch_bounds__(256)
void wgemm_kernel(const bf16* __restrict__ A, const bf16* __restrict__ B,
                  const float* __restrict__ bias, void* __restrict__ Cout,
                  int N, int K)
{
    __shared__ __align__(16) char sm[34816];
    bf16* As = (bf16*)sm;
    bf16* Bs = As + 128 * AST;
    float* stage = (float*)sm;

    int tid = threadIdx.x;
    int bm = blockIdx.y * 128, bn = blockIdx.x * 64;
    int wid = tid >> 5;
    int wm = (wid >> 1) * 32, wn = (wid & 1) * 32;

    wmma::fragment<wmma::accumulator, 16, 16, 16, float> acc[2][2];
#pragma unroll
    for (int i = 0; i < 2; i++)
#pragma unroll
        for (int j = 0; j < 2; j++) wmma::fill_fragment(acc[i][j], 0.f);

    for (int k0 = 0; k0 < K; k0 += 64) {
#pragma unroll 4
        for (int u = tid; u < 1024; u += 256) {
            int r = u >> 3, j = u & 7;
            *(float4*)((char*)As + r * (AST * 2) + j * 16) =
                *(const float4*)(A + (size_t)(bm + r) * K + k0 + j * 8);
        }
#pragma unroll 2
        for (int u = tid; u < 512; u += 256) {
            int r = u >> 3, j = u & 7;
            float4 v = make_float4(0.f, 0.f, 0.f, 0.f);
            if (bn + r < N)
                v = *(const float4*)(B + (size_t)(bn + r) * K + k0 + j * 8);
            *(float4*)((char*)Bs + r * (AST * 2) + j * 16) = v;
        }
        __syncthreads();
#pragma unroll
        for (int kk = 0; kk < 4; kk++) {
            wmma::fragment<wmma::matrix_a, 16, 16, 16, bf16, wmma::row_major> af[2];
#pragma unroll
            for (int i = 0; i < 2; i++)
                wmma::load_matrix_sync(af[i], As + (wm + i * 16) * AST + kk * 16, AST);
#pragma unroll
            for (int j = 0; j < 2; j++) {
                wmma::fragment<wmma::matrix_b, 16, 16, 16, bf16, wmma::col_major> bfj;
                wmma::load_matrix_sync(bfj, Bs + (wn + j * 16) * AST + kk * 16, AST);
                wmma::mma_sync(acc[0][j], af[0], bfj, acc[0][j]);
                wmma::mma_sync(acc[1][j], af[1], bfj, acc[1][j]);
            }
        }
        __syncthreads();
    }

#pragma unroll
    for (int i = 0; i < 2; i++)
#pragma unroll
        for (int j = 0; j < 2; j++)
            wmma::store_matrix_sync(stage + (wm + i * 16) * CST + wn + j * 16,
                                    acc[i][j], CST, wmma::mem_row_major);
    __syncthreads();

#pragma unroll 4
    for (int u = tid; u < 8192; u += 256) {
        int r = u >> 6, c = u & 63;
        int n = bn + c;
        if (n >= N) continue;
        float v = stage[r * CST + c] + (bias ? bias[n] : 0.f);
        if (OUT_BF16) ((bf16*)Cout)[(size_t)(bm + r) * N + n] = __float2bfloat16(v);
        else          ((float*)Cout)[(size_t)(bm + r) * N + n] = v;
    }
}

// ---------------- depthwise causal conv1d + silu --------------------------------
__global__ void conv1d_silu_kernel(const float* __restrict__ cw, const float* __restrict__ cb) {
    int gid = blockIdx.x * 256 + threadIdx.x;
    if (gid >= ROWS * DI) return;
    int idx = gid / DI, d = gid - idx * DI;
    int l = idx & 1023;
    float s = cb[d];
#pragma unroll
    for (int k = 0; k < 4; k++) {
        int ll = l - 3 + k;
        if (ll >= 0)
            s = fmaf(g_xz[(size_t)(idx - 3 + k) * 768 + d], cw[d * 4 + k], s);
    }
    float r = s / (1.f + expf(-s));
    g_uact[gid] = r;
    g_uactb[gid] = __float2bfloat16(r);
}

// ---------------- dt_proj + softplus -------------------------------------------
__global__ void dtproj_kernel(const float* __restrict__ dpw, const float* __restrict__ dpb) {
    int idx = blockIdx.x;
    int d = threadIdx.x;
    __shared__ float dts[DTR];
    if (d < DTR) dts[d] = g_dbc[idx * DBC_N + d];
    __syncthreads();
    float s = dpb[d];
#pragma unroll
    for (int r = 0; r < DTR; r++) s = fmaf(dts[r], dpw[d * DTR + r], s);
    g_delta[(size_t)idx * DI + d] = fmaxf(s, 0.f) + log1pf(expf(-fabsf(s)));
}

// ---------------- selective scan (fast ex2 chain, 2-deep prefetch) --------------
__global__ __launch_bounds__(128)
void scan_kernel(const float* __restrict__ A_log, const float* __restrict__ Dv) {
    int tid = threadIdx.x;
    int g = blockIdx.x * 8 + (tid >> 4);
    int lane = tid & 15;
    int b = g / DI, d = g - b * DI;
    // pre-scale A by log2(e) so the chain exp is a single MUFU ex2
    float An2 = -expf(A_log[d * DS + lane]) * 1.44269504f;
    float Dd = Dv[d];
    float h = 0.f;
    int base = b * LSEQ;

    float delta = g_delta[(size_t)base * DI + d];
    float uu    = g_uact [(size_t)base * DI + d];
    float Bn    = g_dbc[base * DBC_N + DTR + lane];
    float Cn    = g_dbc[base * DBC_N + DTR + DS + lane];

    for (int l = 0; l < LSEQ; l++) {
        int idx = base + l;
        int nidx = idx + ((l < LSEQ - 1) ? 1 : 0);
        float nd = g_delta[(size_t)nidx * DI + d];
        float nu = g_uact [(size_t)nidx * DI + d];
        float nB = g_dbc[nidx * DBC_N + DTR + lane];
        float nC = g_dbc[nidx * DBC_N + DTR + DS + lane];

        h = fmaf(ex2_approx(delta * An2), h, delta * Bn * uu);
        float t = h * Cn;
        t += __shfl_xor_sync(0xffffffffu, t, 8);
        t += __shfl_xor_sync(0xffffffffu, t, 4);
        t += __shfl_xor_sync(0xffffffffu, t, 2);
        t += __shfl_xor_sync(0xffffffffu, t, 1);
        if (lane == 0) {
            float z = g_xz[(size_t)idx * 768 + DI + d];
            float y = fmaf(uu, Dd, t);
            g_ygb[(size_t)idx * DI + d] = __float2bfloat16(y * (z / (1.f + expf(-z))));
        }
        delta = nd; uu = nu; Bn = nB; Cn = nC;
    }
}

// ---------------- WMMA bf16 deconv: cp.async double-buffered K-pipeline ---------
#define KC 64
#define BST 72
#define BUFB (128 * BST * 2)
#define SSTRIDE 132
__global__ __launch_bounds__(256, 2)
void deconv_wmma_kernel(const bf16* __restrict__ G, const bf16* __restrict__ Wt,
                        const float* __restrict__ bias, bf16* __restrict__ out)
{
    extern __shared__ char smem[];
    float* stage = (float*)smem;
    uint32_t sa[2] = { smem_u32(smem),             smem_u32(smem + BUFB) };
    uint32_t sb[2] = { smem_u32(smem + 2 * BUFB),  smem_u32(smem + 3 * BUFB) };

    int tid = threadIdx.x;
    int bn = blockIdx.x * 128, bm = blockIdx.y * 128;
    float bv = bias[bn >> 8];

    const bf16* gsrc = G + (size_t)bm * DM;
    const bf16* wsrc = Wt + (size_t)bn * DM;

    int fr = tid >> 3, fj = (tid & 7) * 8;
    auto fill = [&](int buf, int c) {
        int koff = c * KC + fj;
#pragma unroll
        for (int rr = 0; rr < 128; rr += 32) {
            int r = fr + rr;
            uint32_t da = sa[buf] + (uint32_t)(r * BST + fj) * 2;
            uint32_t db = sb[buf] + (uint32_t)(r * BST + fj) * 2;
            asm volatile("cp.async.cg.shared.global [%0], [%1], 16;"
                         :: "r"(da), "l"(gsrc + (size_t)r * DM + koff));
            asm volatile("cp.async.cg.shared.global [%0], [%1], 16;"
                         :: "r"(db), "l"(wsrc + (size_t)r * DM + koff));
        }
        asm volatile("cp.async.commit_group;");
    };

    int wid = tid >> 5;
    int wm = (wid >> 2) * 64;
    int wn = (wid & 3) * 32;

    wmma::fragment<wmma::accumulator, 16, 16, 16, float> acc[4][2];
#pragma unroll
    for (int i = 0; i < 4; i++)
#pragma unroll
        for (int j = 0; j < 2; j++) wmma::fill_fragment(acc[i][j], 0.f);

    const bf16* Ab[2] = { (const bf16*)smem, (const bf16*)(smem + BUFB) };
    const bf16* Bb[2] = { (const bf16*)(smem + 2 * BUFB), (const bf16*)(smem + 3 * BUFB) };
    auto compute = [&](int buf) {
#pragma unroll
        for (int kk = 0; kk < KC; kk += 16) {
            wmma::fragment<wmma::matrix_b, 16, 16, 16, bf16, wmma::col_major> bf_[2];
#pragma unroll
            for (int j = 0; j < 2; j++)
                wmma::load_matrix_sync(bf_[j], Bb[buf] + (wn + j * 16) * BST + kk, BST);
#pragma unroll
            for (int i = 0; i < 4; i++) {
                wmma::fragment<wmma::matrix_a, 16, 16, 16, bf16, wmma::row_major> afi;
                wmma::load_matrix_sync(afi, Ab[buf] + (wm + i * 16) * BST + kk, BST);
                wmma::mma_sync(acc[i][0], afi, bf_[0], acc[i][0]);
                wmma::mma_sync(acc[i][1], afi, bf_[1], acc[i][1]);
            }
        }
    };

    fill(0, 0);
    fill(1, 1);
    asm volatile("cp.async.wait_group 1;");
    __syncthreads();
    compute(0);
    __syncthreads();
    fill(0, 2);
    asm volatile("cp.async.wait_group 1;");
    __syncthreads();
    compute(1);
    __syncthreads();
    asm volatile("cp.async.wait_group 0;");
    __syncthreads();
    compute(0);

#pragma unroll
    for (int i = 0; i < 4; i++)
#pragma unroll
        for (int j = 0; j < 2; j++)
#pragma unroll
            for (int t = 0; t < acc[i][j].num_elements; t++)
                acc[i][j].x[t] = fmaxf(acc[i][j].x[t] + bv, 0.f);

    __syncthreads();
#pragma unroll
    for (int i = 0; i < 4; i++)
#pragma unroll
        for (int j = 0; j < 2; j++)
            wmma::store_matrix_sync(stage + (wm + i * 16) * SSTRIDE + wn + j * 16,
                                    acc[i][j], SSTRIDE, wmma::mem_row_major);
    __syncthreads();

    {
        int b_img  = bm >> 10;
        int h_base = (bm & 1023) >> 5;
        int dch    = bn >> 8;
        int p_base = (bn >> 4) & 15;
        bf16* dst = out + (size_t)b_img * 16777216 + (size_t)dch * 262144;
#pragma unroll 8
        for (int i = tid; i < 2048; i += 256) {
            int row = i >> 6;
            int c8  = (i & 63) * 8;
            int h = row >> 3, p = row & 7;
            int w = c8 >> 4, q = c8 & 15;
            const float* sp = stage + (h * 32 + w) * SSTRIDE + p * 16 + q;
            float4 v0 = *(const float4*)sp;
            float4 v1 = *(const float4*)(sp + 4);
            __nv_bfloat162 o0 = __floats2bfloat162_rn(v0.x, v0.y);
            __nv_bfloat162 o1 = __floats2bfloat162_rn(v0.z, v0.w);
            __nv_bfloat162 o2 = __floats2bfloat162_rn(v1.x, v1.y);
            __nv_bfloat162 o3 = __floats2bfloat162_rn(v1.z, v1.w);
            uint4 pkv;
            pkv.x = *(uint32_t*)&o0; pkv.y = *(uint32_t*)&o1;
            pkv.z = *(uint32_t*)&o2; pkv.w = *(uint32_t*)&o3;
            *(uint4*)(dst + (size_t)((h_base + h) * 16 + p_base + p) * 512 + c8) = pkv;
        }
    }
}

// ---------------- 3x3 conv + sigmoid: 128x8 tiles, coalesced 264B rows ----------
#define C3_TS 132     // tile row stride in floats (128 px + 4 halo)
__global__ __launch_bounds__(256)
void conv3_sigmoid_kernel(const float* __restrict__ W, const float* __restrict__ wb,
                          float* __restrict__ out) {
    extern __shared__ char c3sm[];
    u64*   ws2  = (u64*)c3sm;                 // 1728 packed weight pairs (13824 B)
    float* tile = (float*)(c3sm + 13824);     // 8 ch x 10 rows x C3_TS

    int b = blockIdx.z, th = blockIdx.y, tw = blockIdx.x;
    int tid = threadIdx.x;
    for (int i = tid; i < 1728; i += 256) { float w = W[i]; ws2[i] = pk2(w, w); }

    int py = tid >> 5;                // 0..7 (output row in tile)
    int pxg = (tid & 31) * 4;         // output col group base (0..124)
    int y0 = th * 8 - 1;
    int x0 = tw * 128 - 2;

    u64 accA[3], accB[3];
#pragma unroll
    for (int oc = 0; oc < 3; oc++) { accA[oc] = pk2(wb[oc], wb[oc]); accB[oc] = accA[oc]; }

    int lr = tid >> 5;                // loader row 0..7 (plus +8 pass)
    int lj = tid & 31;                // pair-column stride 32 over 66

    for (int c0 = 0; c0 < 64; c0 += 8) {
        __syncthreads();
        // load 8 channels x 10 rows x 66 bf16-pairs, fully coalesced (128B/warp)
#pragma unroll
        for (int dl = 0; dl < 8; dl++) {
            const bf16* src = g_decb + (((size_t)b * 64 + c0 + dl) * 512) * 512;
            float* trow = tile + dl * 10 * C3_TS;
#pragma unroll
            for (int r0 = 0; r0 < 16; r0 += 8) {
                int r = lr + r0;
                if (r < 10) {
                    int yy = y0 + r;
                    bool yok = (yy >= 0 && yy < 512);
                    const bf16* srow = src + (size_t)yy * 512;
                    for (int j = lj; j < 66; j += 32) {
                        int xx = x0 + j * 2;
                        float f0 = 0.f, f1 = 0.f;
                        if (yok) {
                            if (xx >= 0 && xx + 1 < 512) {
                                __nv_bfloat162 v = *(const __nv_bfloat162*)(srow + xx);
                                f0 = __bfloat162float(v.x); f1 = __bfloat162float(v.y);
                            } else {
                                if (xx >= 0 && xx < 512)         f0 = __bfloat162float(srow[xx]);
                                if (xx + 1 >= 0 && xx + 1 < 512) f1 = __bfloat162float(srow[xx + 1]);
                            }
                        }
                        trow[r * C3_TS + j * 2]     = f0;
                        trow[r * C3_TS + j * 2 + 1] = f1;
                    }
                }
            }
        }
        __syncthreads();

#pragma unroll
        for (int dl = 0; dl < 8; dl++) {
            int d = c0 + dl;
            const u64* w0 = ws2 + d * 9;
            const u64* w1 = ws2 + (64 + d) * 9;
            const u64* w2 = ws2 + (128 + d) * 9;
            const float* trow = tile + dl * 10 * C3_TS + pxg + 1;
#pragma unroll
            for (int dy = 0; dy < 3; dy++) {
                const float* t = trow + (py + dy) * C3_TS;
                float v0 = t[0], v1 = t[1], v2 = t[2], v3 = t[3], v4 = t[4], v5 = t[5];
                u64 p01 = pk2(v0, v1), p12 = pk2(v1, v2), p23 = pk2(v2, v3);
                u64 p34 = pk2(v3, v4), p45 = pk2(v4, v5);
                int wi = dy * 3;
                fma2(accA[0], p01, w0[wi]); fma2(accA[0], p12, w0[wi+1]); fma2(accA[0], p23, w0[wi+2]);
                fma2(accA[1], p01, w1[wi]); fma2(accA[1], p12, w1[wi+1]); fma2(accA[1], p23, w1[wi+2]);
                fma2(accA[2], p01, w2[wi]); fma2(accA[2], p12, w2[wi+1]); fma2(accA[2], p23, w2[wi+2]);
                fma2(accB[0], p23, w0[wi]); fma2(accB[0], p34, w0[wi+1]); fma2(accB[0], p45, w0[wi+2]);
                fma2(accB[1], p23, w1[wi]); fma2(accB[1], p34, w1[wi+1]); fma2(accB[1], p45, w1[wi+2]);
                fma2(accB[2], p23, w2[wi]); fma2(accB[2], p34, w2[wi+1]); fma2(accB[2], p45, w2[wi+2]);
            }
        }
    }

    int Y = th * 8 + py, X0 = tw * 128 + pxg;
    size_t o = (size_t)b * 3 * 262144 + (size_t)Y * 512 + X0;
#pragma unroll
    for (int oc = 0; oc < 3; oc++) {
        float a0, a1, a2, a3;
        unpk2(a0, a1, accA[oc]);
        unpk2(a2, a3, accB[oc]);
        float* dst = out + o + (size_t)oc * 262144;
        dst[0] = 1.f / (1.f + expf(-a0));
        dst[1] = 1.f / (1.f + expf(-a1));
        dst[2] = 1.f / (1.f + expf(-a2));
        dst[3] = 1.f / (1.f + expf(-a3));
    }
}

// ---------------- launch --------------------------------------------------------
extern "C" void kernel_launch(void* const* d_in, const int* in_sizes, int n_in,
                              void* d_out, int out_size) {
    const float* x         = (const float*)d_in[0];
    const float* patch_w   = (const float*)d_in[1];
    const float* patch_b   = (const float*)d_in[2];
    const float* in_proj_w = (const float*)d_in[3];
    const float* conv1d_w  = (const float*)d_in[4];
    const float* conv1d_b  = (const float*)d_in[5];
    const float* x_proj_w  = (const float*)d_in[6];
    const float* dt_proj_w = (const float*)d_in[7];
    const float* dt_proj_b = (const float*)d_in[8];
    const float* A_log     = (const float*)d_in[9];
    const float* Dv        = (const float*)d_in[10];
    const float* out_proj_w= (const float*)d_in[11];
    const float* deconv_w  = (const float*)d_in[12];
    const float* deconv_b  = (const float*)d_in[13];
    const float* dec_conv_w= (const float*)d_in[14];
    const float* dec_conv_b= (const float*)d_in[15];
    float* out = (float*)d_out;

    bf16 *Apeb, *seqb, *uactb, *ygb, *goutb, *wtb, *decb, *pwb, *ipwb, *xpwb, *opwb;
    float *xz, *uact, *dbc, *delta;
    cudaGetSymbolAddress((void**)&Apeb, g_Apeb);
    cudaGetSymbolAddress((void**)&seqb, g_seqb);
    cudaGetSymbolAddress((void**)&xz,   g_xz);
    cudaGetSymbolAddress((void**)&uact, g_uact);
    cudaGetSymbolAddress((void**)&uactb,g_uactb);
    cudaGetSymbolAddress((void**)&dbc,  g_dbc);
    cudaGetSymbolAddress((void**)&delta,g_delta);
    cudaGetSymbolAddress((void**)&ygb,  g_ygb);
    cudaGetSymbolAddress((void**)&goutb,g_goutb);
    cudaGetSymbolAddress((void**)&wtb,  g_wtb);
    cudaGetSymbolAddress((void**)&decb, g_decb);
    cudaGetSymbolAddress((void**)&pwb,  g_pwb);
    cudaGetSymbolAddress((void**)&ipwb, g_ipwb);
    cudaGetSymbolAddress((void**)&xpwb, g_xpwb);
    cudaGetSymbolAddress((void**)&opwb, g_opwb);

    const int DSMEM = 4 * BUFB;                              // 73728
    const int C3SMEM = 13824 + 8 * 10 * C3_TS * 4;           // 56064
    cudaFuncSetAttribute(deconv_wmma_kernel,
                         cudaFuncAttributeMaxDynamicSharedMemorySize, DSMEM);
    cudaFuncSetAttribute(conv3_sigmoid_kernel,
                         cudaFuncAttributeMaxDynamicSharedMemorySize, C3SMEM);

    // launches 1-3: independent prep
    im2col_kernel<<<(ROWS * 768 + 255) / 256, 256>>>(x);
    cvt_weights_kernel<<<(W3 + 255)/256, 256>>>(patch_w, in_proj_w, x_proj_w, out_proj_w);
    transpose_w_kernel<<<dim3(NDEC / 32, 6), 256>>>(deconv_w);

    // launch 4: PROBE of conv3 (1/8 grid, reads stale g_decb; its writes into
    // `out` are fully overwritten by the real conv3 at the end)
    conv3_sigmoid_kernel<<<dim3(4, 64, 1), 256, C3SMEM>>>(dec_conv_w, dec_conv_b, out);

    // real pipeline
    wgemm_kernel<true><<<dim3(3, 64), 256>>>(Apeb, pwb, patch_b, seqb, DM, 768);
    wgemm_kernel<false><<<dim3(12, 64), 256>>>(seqb, ipwb, nullptr, xz, 2 * DI, DM);
    conv1d_silu_kernel<<<(ROWS * DI + 255) / 256, 256>>>(conv1d_w, conv1d_b);
    wgemm_kernel<false><<<dim3(1, 64), 256>>>(uactb, xpwb, nullptr, dbc, DBC_N, DI);
    dtproj_kernel<<<ROWS, DI>>>(dt_proj_w, dt_proj_b);
    scan_kernel<<<384, 128>>>(A_log, Dv);
    wgemm_kernel<true><<<dim3(3, 64), 256>>>(ygb, opwb, nullptr, goutb, DM, DI);
    deconv_wmma_kernel<<<dim3(128, 64), 256, DSMEM>>>(goutb, wtb, deconv_b, decb);
    conv3_sigmoid_kernel<<<dim3(4, 64, 8), 256, C3SMEM>>>(dec_conv_w, dec_conv_b, out);
}

// round 11
// speedup vs baseline: 1.1095x; 1.1095x over previous
#include <cuda_runtime.h>
#include <cuda_bf16.h>
#include <mma.h>
#include <math.h>
#include <stdint.h>

using namespace nvcuda;

#define BATCH 8
#define LSEQ  1024
#define ROWS  (BATCH*LSEQ)   // 8192
#define DM    192
#define DI    384
#define DS    16
#define DTR   12
#define DBC_N (DTR + 2*DS)   // 44
#define NDEC  16384

typedef __nv_bfloat16 bf16;
typedef unsigned long long u64;

// ---------------- scratch -------------------------------------------------------
__device__ bf16  g_Apeb[ROWS*768];
__device__ bf16  g_seqb[ROWS*DM];
__device__ float g_xz  [ROWS*2*DI];
__device__ float g_uact[ROWS*DI];
__device__ bf16  g_uactb[ROWS*DI];
__device__ float g_dbc [ROWS*DBC_N];
__device__ float g_delta[ROWS*DI];
__device__ bf16  g_ygb [ROWS*DI];
__device__ bf16  g_goutb[ROWS*DM];
__device__ bf16  g_wtb [(size_t)NDEC*DM];
__device__ bf16  g_decb[(size_t)BATCH*64*512*512];   // 268 MB
__device__ bf16  g_pwb [DM*768];
__device__ bf16  g_ipwb[2*DI*DM];
__device__ bf16  g_xpwb[DBC_N*DI];
__device__ bf16  g_opwb[DM*DI];

// ---------------- helpers -------------------------------------------------------
__device__ __forceinline__ u64 pk2(float lo, float hi) {
    u64 r; asm("mov.b64 %0, {%1, %2};" : "=l"(r) : "f"(lo), "f"(hi)); return r;
}
__device__ __forceinline__ void unpk2(float& lo, float& hi, u64 v) {
    asm("mov.b64 {%0, %1}, %2;" : "=f"(lo), "=f"(hi) : "l"(v));
}
__device__ __forceinline__ void fma2(u64& acc, u64 a, u64 b) {
    asm("fma.rn.f32x2 %0, %1, %2, %0;" : "+l"(acc) : "l"(a), "l"(b));
}
__device__ __forceinline__ uint32_t smem_u32(const void* p) {
    uint32_t a;
    asm("{ .reg .u64 t; cvta.to.shared.u64 t, %1; cvt.u32.u64 %0, t; }" : "=r"(a) : "l"(p));
    return a;
}
__device__ __forceinline__ float ex2_approx(float x) {
    float r; asm("ex2.approx.f32 %0, %1;" : "=f"(r) : "f"(x)); return r;
}

// ---------------- merged weight converts ----------------------------------------
#define W0 (DM*768)
#define W1 (W0 + 2*DI*DM)
#define W2 (W1 + DBC_N*DI)
#define W3 (W2 + DM*DI)
__global__ void cvt_weights_kernel(const float* __restrict__ pw, const float* __restrict__ ipw,
                                   const float* __restrict__ xpw, const float* __restrict__ opw) {
    int i = blockIdx.x * 256 + threadIdx.x;
    if (i >= W3) return;
    if (i < W0)      g_pwb [i]      = __float2bfloat16(pw [i]);
    else if (i < W1) g_ipwb[i - W0] = __float2bfloat16(ipw[i - W0]);
    else if (i < W2) g_xpwb[i - W1] = __float2bfloat16(xpw[i - W1]);
    else             g_opwb[i - W2] = __float2bfloat16(opw[i - W2]);
}

__global__ void transpose_w_kernel(const float* __restrict__ W) {
    __shared__ float t[32][33];
    int bn = blockIdx.x * 32, bk = blockIdx.y * 32;
    int tx = threadIdx.x & 31, ty = threadIdx.x >> 5;
#pragma unroll
    for (int i = ty; i < 32; i += 8) {
        int k = bk + i;
        t[i][tx] = (k < DM) ? W[(size_t)k * NDEC + bn + tx] : 0.f;
    }
    __syncthreads();
#pragma unroll
    for (int i = ty; i < 32; i += 8) {
        int k = bk + tx;
        if (k < DM)
            g_wtb[(size_t)(bn + i) * DM + k] = __float2bfloat16(t[tx][i]);
    }
}

// ---------------- im2col (writes bf16) ------------------------------------------
__global__ void im2col_kernel(const float* __restrict__ x) {
    int gid = blockIdx.x * 256 + threadIdx.x;
    if (gid >= ROWS * 768) return;
    int row = gid / 768, k = gid - row * 768;
    int c = k >> 8, rem = k & 255, p = rem >> 4, q = rem & 15;
    int b = row >> 10, hw = row & 1023, h = hw >> 5, w = hw & 31;
    g_Apeb[gid] = __float2bfloat16(x[((b * 3 + c) * 512 + h * 16 + p) * 512 + w * 16 + q]);
}

// ---------------- generic WMMA bf16 NT GEMM -------------------------------------
#define AST 72
#define CST 68
template<bool OUT_BF16>
__global__ __launch_bounds__(256)
void wgemm_kernel(const bf16* __restrict__ A, const bf16* __restrict__ B,
                  const float* __restrict__ bias, void* __restrict__ Cout,
                  int N, int K)
{
    __shared__ __align__(16) char sm[34816];
    bf16* As = (bf16*)sm;
    bf16* Bs = As + 128 * AST;
    float* stage = (float*)sm;

    int tid = threadIdx.x;
    int bm = blockIdx.y * 128, bn = blockIdx.x * 64;
    int wid = tid >> 5;
    int wm = (wid >> 1) * 32, wn = (wid & 1) * 32;

    wmma::fragment<wmma::accumulator, 16, 16, 16, float> acc[2][2];
#pragma unroll
    for (int i = 0; i < 2; i++)
#pragma unroll
        for (int j = 0; j < 2; j++) wmma::fill_fragment(acc[i][j], 0.f);

    for (int k0 = 0; k0 < K; k0 += 64) {
#pragma unroll 4
        for (int u = tid; u < 1024; u += 256) {
            int r = u >> 3, j = u & 7;
            *(float4*)((char*)As + r * (AST * 2) + j * 16) =
                *(const float4*)(A + (size_t)(bm + r) * K + k0 + j * 8);
        }
#pragma unroll 2
        for (int u = tid; u < 512; u += 256) {
            int r = u >> 3, j = u & 7;
            float4 v = make_float4(0.f, 0.f, 0.f, 0.f);
            if (bn + r < N)
                v = *(const float4*)(B + (size_t)(bn + r) * K + k0 + j * 8);
            *(float4*)((char*)Bs + r * (AST * 2) + j * 16) = v;
        }
        __syncthreads();
#pragma unroll
        for (int kk = 0; kk < 4; kk++) {
            wmma::fragment<wmma::matrix_a, 16, 16, 16, bf16, wmma::row_major> af[2];
#pragma unroll
            for (int i = 0; i < 2; i++)
                wmma::load_matrix_sync(af[i], As + (wm + i * 16) * AST + kk * 16, AST);
#pragma unroll
            for (int j = 0; j < 2; j++) {
                wmma::fragment<wmma::matrix_b, 16, 16, 16, bf16, wmma::col_major> bfj;
                wmma::load_matrix_sync(bfj, Bs + (wn + j * 16) * AST + kk * 16, AST);
                wmma::mma_sync(acc[0][j], af[0], bfj, acc[0][j]);
                wmma::mma_sync(acc[1][j], af[1], bfj, acc[1][j]);
            }
        }
        __syncthreads();
    }

#pragma unroll
    for (int i = 0; i < 2; i++)
#pragma unroll
        for (int j = 0; j < 2; j++)
            wmma::store_matrix_sync(stage + (wm + i * 16) * CST + wn + j * 16,
                                    acc[i][j], CST, wmma::mem_row_major);
    __syncthreads();

#pragma unroll 4
    for (int u = tid; u < 8192; u += 256) {
        int r = u >> 6, c = u & 63;
        int n = bn + c;
        if (n >= N) continue;
        float v = stage[r * CST + c] + (bias ? bias[n] : 0.f);
        if (OUT_BF16) ((bf16*)Cout)[(size_t)(bm + r) * N + n] = __float2bfloat16(v);
        else          ((float*)Cout)[(size_t)(bm + r) * N + n] = v;
    }
}

// ---------------- depthwise causal conv1d + silu --------------------------------
__global__ void conv1d_silu_kernel(const float* __restrict__ cw, const float* __restrict__ cb) {
    int gid = blockIdx.x * 256 + threadIdx.x;
    if (gid >= ROWS * DI) return;
    int idx = gid / DI, d = gid - idx * DI;
    int l = idx & 1023;
    float s = cb[d];
#pragma unroll
    for (int k = 0; k < 4; k++) {
        int ll = l - 3 + k;
        if (ll >= 0)
            s = fmaf(g_xz[(size_t)(idx - 3 + k) * 768 + d], cw[d * 4 + k], s);
    }
    float r = s / (1.f + expf(-s));
    g_uact[gid] = r;
    g_uactb[gid] = __float2bfloat16(r);
}

// ---------------- dt_proj + softplus -------------------------------------------
__global__ void dtproj_kernel(const float* __restrict__ dpw, const float* __restrict__ dpb) {
    int idx = blockIdx.x;
    int d = threadIdx.x;
    __shared__ float dts[DTR];
    if (d < DTR) dts[d] = g_dbc[idx * DBC_N + d];
    __syncthreads();
    float s = dpb[d];
#pragma unroll
    for (int r = 0; r < DTR; r++) s = fmaf(dts[r], dpw[d * DTR + r], s);
    g_delta[(size_t)idx * DI + d] = fmaxf(s, 0.f) + log1pf(expf(-fabsf(s)));
}

// ---------------- selective scan (fast ex2 chain, 2-deep prefetch) --------------
__global__ __launch_bounds__(128)
void scan_kernel(const float* __restrict__ A_log, const float* __restrict__ Dv) {
    int tid = threadIdx.x;
    int g = blockIdx.x * 8 + (tid >> 4);
    int lane = tid & 15;
    int b = g / DI, d = g - b * DI;
    float An2 = -expf(A_log[d * DS + lane]) * 1.44269504f;
    float Dd = Dv[d];
    float h = 0.f;
    int base = b * LSEQ;

    float delta = g_delta[(size_t)base * DI + d];
    float uu    = g_uact [(size_t)base * DI + d];
    float Bn    = g_dbc[base * DBC_N + DTR + lane];
    float Cn    = g_dbc[base * DBC_N + DTR + DS + lane];

    for (int l = 0; l < LSEQ; l++) {
        int idx = base + l;
        int nidx = idx + ((l < LSEQ - 1) ? 1 : 0);
        float nd = g_delta[(size_t)nidx * DI + d];
        float nu = g_uact [(size_t)nidx * DI + d];
        float nB = g_dbc[nidx * DBC_N + DTR + lane];
        float nC = g_dbc[nidx * DBC_N + DTR + DS + lane];

        h = fmaf(ex2_approx(delta * An2), h, delta * Bn * uu);
        float t = h * Cn;
        t += __shfl_xor_sync(0xffffffffu, t, 8);
        t += __shfl_xor_sync(0xffffffffu, t, 4);
        t += __shfl_xor_sync(0xffffffffu, t, 2);
        t += __shfl_xor_sync(0xffffffffu, t, 1);
        if (lane == 0) {
            float z = g_xz[(size_t)idx * 768 + DI + d];
            float y = fmaf(uu, Dd, t);
            g_ygb[(size_t)idx * DI + d] = __float2bfloat16(y * (z / (1.f + expf(-z))));
        }
        delta = nd; uu = nu; Bn = nB; Cn = nC;
    }
}

// ---------------- WMMA bf16 deconv: cp.async double-buffered K-pipeline ---------
#define KC 64
#define BST 72
#define BUFB (128 * BST * 2)
#define SSTRIDE 132
__global__ __launch_bounds__(256, 2)
void deconv_wmma_kernel(const bf16* __restrict__ G, const bf16* __restrict__ Wt,
                        const float* __restrict__ bias, bf16* __restrict__ out)
{
    extern __shared__ char smem[];
    float* stage = (float*)smem;
    uint32_t sa[2] = { smem_u32(smem),             smem_u32(smem + BUFB) };
    uint32_t sb[2] = { smem_u32(smem + 2 * BUFB),  smem_u32(smem + 3 * BUFB) };

    int tid = threadIdx.x;
    int bn = blockIdx.x * 128, bm = blockIdx.y * 128;
    float bv = bias[bn >> 8];

    const bf16* gsrc = G + (size_t)bm * DM;
    const bf16* wsrc = Wt + (size_t)bn * DM;

    int fr = tid >> 3, fj = (tid & 7) * 8;
    auto fill = [&](int buf, int c) {
        int koff = c * KC + fj;
#pragma unroll
        for (int rr = 0; rr < 128; rr += 32) {
            int r = fr + rr;
            uint32_t da = sa[buf] + (uint32_t)(r * BST + fj) * 2;
            uint32_t db = sb[buf] + (uint32_t)(r * BST + fj) * 2;
            asm volatile("cp.async.cg.shared.global [%0], [%1], 16;"
                         :: "r"(da), "l"(gsrc + (size_t)r * DM + koff));
            asm volatile("cp.async.cg.shared.global [%0], [%1], 16;"
                         :: "r"(db), "l"(wsrc + (size_t)r * DM + koff));
        }
        asm volatile("cp.async.commit_group;");
    };

    int wid = tid >> 5;
    int wm = (wid >> 2) * 64;
    int wn = (wid & 3) * 32;

    wmma::fragment<wmma::accumulator, 16, 16, 16, float> acc[4][2];
#pragma unroll
    for (int i = 0; i < 4; i++)
#pragma unroll
        for (int j = 0; j < 2; j++) wmma::fill_fragment(acc[i][j], 0.f);

    const bf16* Ab[2] = { (const bf16*)smem, (const bf16*)(smem + BUFB) };
    const bf16* Bb[2] = { (const bf16*)(smem + 2 * BUFB), (const bf16*)(smem + 3 * BUFB) };
    auto compute = [&](int buf) {
#pragma unroll
        for (int kk = 0; kk < KC; kk += 16) {
            wmma::fragment<wmma::matrix_b, 16, 16, 16, bf16, wmma::col_major> bf_[2];
#pragma unroll
            for (int j = 0; j < 2; j++)
                wmma::load_matrix_sync(bf_[j], Bb[buf] + (wn + j * 16) * BST + kk, BST);
#pragma unroll
            for (int i = 0; i < 4; i++) {
                wmma::fragment<wmma::matrix_a, 16, 16, 16, bf16, wmma::row_major> afi;
                wmma::load_matrix_sync(afi, Ab[buf] + (wm + i * 16) * BST + kk, BST);
                wmma::mma_sync(acc[i][0], afi, bf_[0], acc[i][0]);
                wmma::mma_sync(acc[i][1], afi, bf_[1], acc[i][1]);
            }
        }
    };

    fill(0, 0);
    fill(1, 1);
    asm volatile("cp.async.wait_group 1;");
    __syncthreads();
    compute(0);
    __syncthreads();
    fill(0, 2);
    asm volatile("cp.async.wait_group 1;");
    __syncthreads();
    compute(1);
    __syncthreads();
    asm volatile("cp.async.wait_group 0;");
    __syncthreads();
    compute(0);

#pragma unroll
    for (int i = 0; i < 4; i++)
#pragma unroll
        for (int j = 0; j < 2; j++)
#pragma unroll
            for (int t = 0; t < acc[i][j].num_elements; t++)
                acc[i][j].x[t] = fmaxf(acc[i][j].x[t] + bv, 0.f);

    __syncthreads();
#pragma unroll
    for (int i = 0; i < 4; i++)
#pragma unroll
        for (int j = 0; j < 2; j++)
            wmma::store_matrix_sync(stage + (wm + i * 16) * SSTRIDE + wn + j * 16,
                                    acc[i][j], SSTRIDE, wmma::mem_row_major);
    __syncthreads();

    {
        int b_img  = bm >> 10;
        int h_base = (bm & 1023) >> 5;
        int dch    = bn >> 8;
        int p_base = (bn >> 4) & 15;
        bf16* dst = out + (size_t)b_img * 16777216 + (size_t)dch * 262144;
#pragma unroll 8
        for (int i = tid; i < 2048; i += 256) {
            int row = i >> 6;
            int c8  = (i & 63) * 8;
            int h = row >> 3, p = row & 7;
            int w = c8 >> 4, q = c8 & 15;
            const float* sp = stage + (h * 32 + w) * SSTRIDE + p * 16 + q;
            float4 v0 = *(const float4*)sp;
            float4 v1 = *(const float4*)(sp + 4);
            __nv_bfloat162 o0 = __floats2bfloat162_rn(v0.x, v0.y);
            __nv_bfloat162 o1 = __floats2bfloat162_rn(v0.z, v0.w);
            __nv_bfloat162 o2 = __floats2bfloat162_rn(v1.x, v1.y);
            __nv_bfloat162 o3 = __floats2bfloat162_rn(v1.z, v1.w);
            uint4 pkv;
            pkv.x = *(uint32_t*)&o0; pkv.y = *(uint32_t*)&o1;
            pkv.z = *(uint32_t*)&o2; pkv.w = *(uint32_t*)&o3;
            *(uint4*)(dst + (size_t)((h_base + h) * 16 + p_base + p) * 512 + c8) = pkv;
        }
    }
}

// ---------------- 3x3 conv + sigmoid: conflict-free LDS.128 version -------------
// tile 128 wide x 8 high; 8-channel chunks; per (ch,dy): two aligned float4 LDS
#define C3_TS 132     // row stride in floats (multiple of 4 -> 16B alignment holds)
__global__ __launch_bounds__(256)
void conv3_sigmoid_kernel(const float* __restrict__ W, const float* __restrict__ wb,
                          float* __restrict__ out) {
    extern __shared__ char c3sm[];
    u64*   ws2  = (u64*)c3sm;                 // 1728 packed weight pairs (13824 B)
    float* tile = (float*)(c3sm + 13824);     // 8 ch x 10 rows x C3_TS

    int b = blockIdx.z, th = blockIdx.y, tw = blockIdx.x;
    int tid = threadIdx.x;
    for (int i = tid; i < 1728; i += 256) { float w = W[i]; ws2[i] = pk2(w, w); }

    int py = tid >> 5;                // 0..7 output row
    int pxg = (tid & 31) * 4;         // output col group (0,4,...,124) — 16B aligned
    int y0 = th * 8 - 1;
    int x0 = tw * 128 - 2;

    u64 accA[3], accB[3];
#pragma unroll
    for (int oc = 0; oc < 3; oc++) { accA[oc] = pk2(wb[oc], wb[oc]); accB[oc] = accA[oc]; }

    int lr = tid >> 5;                // loader row 0..7 (+8 second pass)
    int lj = tid & 31;                // pair-column 0..31 (stride 32 over 66)

    for (int c0 = 0; c0 < 64; c0 += 8) {
        __syncthreads();
#pragma unroll
        for (int dl = 0; dl < 8; dl++) {
            const bf16* src = g_decb + (((size_t)b * 64 + c0 + dl) * 512) * 512;
            float* trow = tile + dl * 10 * C3_TS;
#pragma unroll
            for (int r0 = 0; r0 < 16; r0 += 8) {
                int r = lr + r0;
                if (r < 10) {
                    int yy = y0 + r;
                    bool yok = (yy >= 0 && yy < 512);
                    const bf16* srow = src + (size_t)yy * 512;
                    for (int j = lj; j < 66; j += 32) {
                        int xx = x0 + j * 2;
                        float2 f = make_float2(0.f, 0.f);
                        if (yok) {
                            if (xx >= 0 && xx + 1 < 512) {
                                __nv_bfloat162 v = *(const __nv_bfloat162*)(srow + xx);
                                f.x = __bfloat162float(v.x); f.y = __bfloat162float(v.y);
                            } else {
                                if (xx >= 0 && xx < 512)         f.x = __bfloat162float(srow[xx]);
                                if (xx + 1 >= 0 && xx + 1 < 512) f.y = __bfloat162float(srow[xx + 1]);
                            }
                        }
                        *(float2*)(trow + r * C3_TS + j * 2) = f;   // STS.64, conflict-free
                    }
                }
            }
        }
        __syncthreads();

#pragma unroll
        for (int dl = 0; dl < 8; dl++) {
            int d = c0 + dl;
            const u64* w0 = ws2 + d * 9;
            const u64* w1 = ws2 + (64 + d) * 9;
            const u64* w2 = ws2 + (128 + d) * 9;
            const float* trow = tile + dl * 10 * C3_TS + pxg;     // 16B aligned
#pragma unroll
            for (int dy = 0; dy < 3; dy++) {
                const float* t = trow + (py + dy) * C3_TS;
                float4 a = *(const float4*)t;          // cols pxg..pxg+3  (LDS.128)
                float4 bq = *(const float4*)(t + 4);   // cols pxg+4..pxg+7
                // needed window = cols pxg+1 .. pxg+6 = a.y..a.w, bq.x..bq.z
                u64 p01 = pk2(a.y, a.z), p12 = pk2(a.z, a.w), p23 = pk2(a.w, bq.x);
                u64 p34 = pk2(bq.x, bq.y), p45 = pk2(bq.y, bq.z);
                int wi = dy * 3;
                fma2(accA[0], p01, w0[wi]); fma2(accA[0], p12, w0[wi+1]); fma2(accA[0], p23, w0[wi+2]);
                fma2(accA[1], p01, w1[wi]); fma2(accA[1], p12, w1[wi+1]); fma2(accA[1], p23, w1[wi+2]);
                fma2(accA[2], p01, w2[wi]); fma2(accA[2], p12, w2[wi+1]); fma2(accA[2], p23, w2[wi+2]);
                fma2(accB[0], p23, w0[wi]); fma2(accB[0], p34, w0[wi+1]); fma2(accB[0], p45, w0[wi+2]);
                fma2(accB[1], p23, w1[wi]); fma2(accB[1], p34, w1[wi+1]); fma2(accB[1], p45, w1[wi+2]);
                fma2(accB[2], p23, w2[wi]); fma2(accB[2], p34, w2[wi+1]); fma2(accB[2], p45, w2[wi+2]);
            }
        }
    }

    int Y = th * 8 + py, X0 = tw * 128 + pxg;
    size_t o = (size_t)b * 3 * 262144 + (size_t)Y * 512 + X0;
#pragma unroll
    for (int oc = 0; oc < 3; oc++) {
        float a0, a1, a2, a3;
        unpk2(a0, a1, accA[oc]);
        unpk2(a2, a3, accB[oc]);
        float* dst = out + o + (size_t)oc * 262144;
        dst[0] = 1.f / (1.f + expf(-a0));
        dst[1] = 1.f / (1.f + expf(-a1));
        dst[2] = 1.f / (1.f + expf(-a2));
        dst[3] = 1.f / (1.f + expf(-a3));
    }
}

// ---------------- launch --------------------------------------------------------
extern "C" void kernel_launch(void* const* d_in, const int* in_sizes, int n_in,
                              void* d_out, int out_size) {
    const float* x         = (const float*)d_in[0];
    const float* patch_w   = (const float*)d_in[1];
    const float* patch_b   = (const float*)d_in[2];
    const float* in_proj_w = (const float*)d_in[3];
    const float* conv1d_w  = (const float*)d_in[4];
    const float* conv1d_b  = (const float*)d_in[5];
    const float* x_proj_w  = (const float*)d_in[6];
    const float* dt_proj_w = (const float*)d_in[7];
    const float* dt_proj_b = (const float*)d_in[8];
    const float* A_log     = (const float*)d_in[9];
    const float* Dv        = (const float*)d_in[10];
    const float* out_proj_w= (const float*)d_in[11];
    const float* deconv_w  = (const float*)d_in[12];
    const float* deconv_b  = (const float*)d_in[13];
    const float* dec_conv_w= (const float*)d_in[14];
    const float* dec_conv_b= (const float*)d_in[15];
    float* out = (float*)d_out;

    bf16 *Apeb, *seqb, *uactb, *ygb, *goutb, *wtb, *decb, *pwb, *ipwb, *xpwb, *opwb;
    float *xz, *uact, *dbc, *delta;
    cudaGetSymbolAddress((void**)&Apeb, g_Apeb);
    cudaGetSymbolAddress((void**)&seqb, g_seqb);
    cudaGetSymbolAddress((void**)&xz,   g_xz);
    cudaGetSymbolAddress((void**)&uact, g_uact);
    cudaGetSymbolAddress((void**)&uactb,g_uactb);
    cudaGetSymbolAddress((void**)&dbc,  g_dbc);
    cudaGetSymbolAddress((void**)&delta,g_delta);
    cudaGetSymbolAddress((void**)&ygb,  g_ygb);
    cudaGetSymbolAddress((void**)&goutb,g_goutb);
    cudaGetSymbolAddress((void**)&wtb,  g_wtb);
    cudaGetSymbolAddress((void**)&decb, g_decb);
    cudaGetSymbolAddress((void**)&pwb,  g_pwb);
    cudaGetSymbolAddress((void**)&ipwb, g_ipwb);
    cudaGetSymbolAddress((void**)&xpwb, g_xpwb);
    cudaGetSymbolAddress((void**)&opwb, g_opwb);

    const int DSMEM = 4 * BUFB;                              // 73728
    const int C3SMEM = 13824 + 8 * 10 * C3_TS * 4;           // 56064
    cudaFuncSetAttribute(deconv_wmma_kernel,
                         cudaFuncAttributeMaxDynamicSharedMemorySize, DSMEM);
    cudaFuncSetAttribute(conv3_sigmoid_kernel,
                         cudaFuncAttributeMaxDynamicSharedMemorySize, C3SMEM);

    im2col_kernel<<<(ROWS * 768 + 255) / 256, 256>>>(x);
    cvt_weights_kernel<<<(W3 + 255)/256, 256>>>(patch_w, in_proj_w, x_proj_w, out_proj_w);
    transpose_w_kernel<<<dim3(NDEC / 32, 6), 256>>>(deconv_w);

    wgemm_kernel<true><<<dim3(3, 64), 256>>>(Apeb, pwb, patch_b, seqb, DM, 768);
    wgemm_kernel<false><<<dim3(12, 64), 256>>>(seqb, ipwb, nullptr, xz, 2 * DI, DM);
    conv1d_silu_kernel<<<(ROWS * DI + 255) / 256, 256>>>(conv1d_w, conv1d_b);
    wgemm_kernel<false><<<dim3(1, 64), 256>>>(uactb, xpwb, nullptr, dbc, DBC_N, DI);
    dtproj_kernel<<<ROWS, DI>>>(dt_proj_w, dt_proj_b);
    scan_kernel<<<384, 128>>>(A_log, Dv);
    wgemm_kernel<true><<<dim3(3, 64), 256>>>(ygb, opwb, nullptr, goutb, DM, DI);
    deconv_wmma_kernel<<<dim3(128, 64), 256, DSMEM>>>(goutb, wtb, deconv_b, decb);
    conv3_sigmoid_kernel<<<dim3(4, 64, 8), 256, C3SMEM>>>(dec_conv_w, dec_conv_b, out);
}

// round 12
// speedup vs baseline: 1.3586x; 1.2245x over previous
#include <cuda_runtime.h>
#include <cuda_bf16.h>
#include <mma.h>
#include <math.h>
#include <stdint.h>

using namespace nvcuda;

#define BATCH 8
#define LSEQ  1024
#define ROWS  (BATCH*LSEQ)   // 8192
#define DM    192
#define DI    384
#define DS    16
#define DTR   12
#define DBC_N (DTR + 2*DS)   // 44
#define NDEC  16384

typedef __nv_bfloat16 bf16;
typedef unsigned long long u64;

// ---------------- scratch -------------------------------------------------------
__device__ bf16  g_Apeb[ROWS*768];
__device__ bf16  g_seqb[ROWS*DM];
__device__ float g_xz  [ROWS*2*DI];
__device__ float g_uact[ROWS*DI];
__device__ bf16  g_uactb[ROWS*DI];
__device__ float g_dbc [ROWS*DBC_N];
__device__ float g_delta[ROWS*DI];
__device__ bf16  g_ygb [ROWS*DI];
__device__ bf16  g_goutb[ROWS*DM];
__device__ bf16  g_wtb [(size_t)NDEC*DM];
__device__ bf16  g_decb[(size_t)BATCH*64*512*512];   // 268 MB
__device__ bf16  g_pwb [DM*768];
__device__ bf16  g_ipwb[2*DI*DM];
__device__ bf16  g_xpwb[DBC_N*DI];
__device__ bf16  g_opwb[DM*DI];

// ---------------- helpers -------------------------------------------------------
__device__ __forceinline__ u64 pk2(float lo, float hi) {
    u64 r; asm("mov.b64 %0, {%1, %2};" : "=l"(r) : "f"(lo), "f"(hi)); return r;
}
__device__ __forceinline__ void unpk2(float& lo, float& hi, u64 v) {
    asm("mov.b64 {%0, %1}, %2;" : "=f"(lo), "=f"(hi) : "l"(v));
}
__device__ __forceinline__ void fma2(u64& acc, u64 a, u64 b) {
    asm("fma.rn.f32x2 %0, %1, %2, %0;" : "+l"(acc) : "l"(a), "l"(b));
}
__device__ __forceinline__ uint32_t smem_u32(const void* p) {
    uint32_t a;
    asm("{ .reg .u64 t; cvta.to.shared.u64 t, %1; cvt.u32.u64 %0, t; }" : "=r"(a) : "l"(p));
    return a;
}
__device__ __forceinline__ float ex2_approx(float x) {
    float r; asm("ex2.approx.f32 %0, %1;" : "=f"(r) : "f"(x)); return r;
}

// ---------------- merged weight converts ----------------------------------------
#define W0 (DM*768)
#define W1 (W0 + 2*DI*DM)
#define W2 (W1 + DBC_N*DI)
#define W3 (W2 + DM*DI)
__global__ void cvt_weights_kernel(const float* __restrict__ pw, const float* __restrict__ ipw,
                                   const float* __restrict__ xpw, const float* __restrict__ opw) {
    int i = blockIdx.x * 256 + threadIdx.x;
    if (i >= W3) return;
    if (i < W0)      g_pwb [i]      = __float2bfloat16(pw [i]);
    else if (i < W1) g_ipwb[i - W0] = __float2bfloat16(ipw[i - W0]);
    else if (i < W2) g_xpwb[i - W1] = __float2bfloat16(xpw[i - W1]);
    else             g_opwb[i - W2] = __float2bfloat16(opw[i - W2]);
}

__global__ void transpose_w_kernel(const float* __restrict__ W) {
    __shared__ float t[32][33];
    int bn = blockIdx.x * 32, bk = blockIdx.y * 32;
    int tx = threadIdx.x & 31, ty = threadIdx.x >> 5;
#pragma unroll
    for (int i = ty; i < 32; i += 8) {
        int k = bk + i;
        t[i][tx] = (k < DM) ? W[(size_t)k * NDEC + bn + tx] : 0.f;
    }
    __syncthreads();
#pragma unroll
    for (int i = ty; i < 32; i += 8) {
        int k = bk + tx;
        if (k < DM)
            g_wtb[(size_t)(bn + i) * DM + k] = __float2bfloat16(t[tx][i]);
    }
}

// ---------------- im2col (writes bf16) ------------------------------------------
__global__ void im2col_kernel(const float* __restrict__ x) {
    int gid = blockIdx.x * 256 + threadIdx.x;
    if (gid >= ROWS * 768) return;
    int row = gid / 768, k = gid - row * 768;
    int c = k >> 8, rem = k & 255, p = rem >> 4, q = rem & 15;
    int b = row >> 10, hw = row & 1023, h = hw >> 5, w = hw & 31;
    g_Apeb[gid] = __float2bfloat16(x[((b * 3 + c) * 512 + h * 16 + p) * 512 + w * 16 + q]);
}

// ---------------- generic WMMA bf16 NT GEMM -------------------------------------
#define AST 72
#define CST 68
template<bool OUT_BF16>
__global__ __launch_bounds__(256)
void wgemm_kernel(const bf16* __restrict__ A, const bf16* __restrict__ B,
                  const float* __restrict__ bias, void* __restrict__ Cout,
                  int N, int K)
{
    __shared__ __align__(16) char sm[34816];
    bf16* As = (bf16*)sm;
    bf16* Bs = As + 128 * AST;
    float* stage = (float*)sm;

    int tid = threadIdx.x;
    int bm = blockIdx.y * 128, bn = blockIdx.x * 64;
    int wid = tid >> 5;
    int wm = (wid >> 1) * 32, wn = (wid & 1) * 32;

    wmma::fragment<wmma::accumulator, 16, 16, 16, float> acc[2][2];
#pragma unroll
    for (int i = 0; i < 2; i++)
#pragma unroll
        for (int j = 0; j < 2; j++) wmma::fill_fragment(acc[i][j], 0.f);

    for (int k0 = 0; k0 < K; k0 += 64) {
#pragma unroll 4
        for (int u = tid; u < 1024; u += 256) {
            int r = u >> 3, j = u & 7;
            *(float4*)((char*)As + r * (AST * 2) + j * 16) =
                *(const float4*)(A + (size_t)(bm + r) * K + k0 + j * 8);
        }
#pragma unroll 2
        for (int u = tid; u < 512; u += 256) {
            int r = u >> 3, j = u & 7;
            float4 v = make_float4(0.f, 0.f, 0.f, 0.f);
            if (bn + r < N)
                v = *(const float4*)(B + (size_t)(bn + r) * K + k0 + j * 8);
            *(float4*)((char*)Bs + r * (AST * 2) + j * 16) = v;
        }
        __syncthreads();
#pragma unroll
        for (int kk = 0; kk < 4; kk++) {
            wmma::fragment<wmma::matrix_a, 16, 16, 16, bf16, wmma::row_major> af[2];
#pragma unroll
            for (int i = 0; i < 2; i++)
                wmma::load_matrix_sync(af[i], As + (wm + i * 16) * AST + kk * 16, AST);
#pragma unroll
            for (int j = 0; j < 2; j++) {
                wmma::fragment<wmma::matrix_b, 16, 16, 16, bf16, wmma::col_major> bfj;
                wmma::load_matrix_sync(bfj, Bs + (wn + j * 16) * AST + kk * 16, AST);
                wmma::mma_sync(acc[0][j], af[0], bfj, acc[0][j]);
                wmma::mma_sync(acc[1][j], af[1], bfj, acc[1][j]);
            }
        }
        __syncthreads();
    }

#pragma unroll
    for (int i = 0; i < 2; i++)
#pragma unroll
        for (int j = 0; j < 2; j++)
            wmma::store_matrix_sync(stage + (wm + i * 16) * CST + wn + j * 16,
                                    acc[i][j], CST, wmma::mem_row_major);
    __syncthreads();

#pragma unroll 4
    for (int u = tid; u < 8192; u += 256) {
        int r = u >> 6, c = u & 63;
        int n = bn + c;
        if (n >= N) continue;
        float v = stage[r * CST + c] + (bias ? bias[n] : 0.f);
        if (OUT_BF16) ((bf16*)Cout)[(size_t)(bm + r) * N + n] = __float2bfloat16(v);
        else          ((float*)Cout)[(size_t)(bm + r) * N + n] = v;
    }
}

// ---------------- depthwise causal conv1d + silu --------------------------------
__global__ void conv1d_silu_kernel(const float* __restrict__ cw, const float* __restrict__ cb) {
    int gid = blockIdx.x * 256 + threadIdx.x;
    if (gid >= ROWS * DI) return;
    int idx = gid / DI, d = gid - idx * DI;
    int l = idx & 1023;
    float s = cb[d];
#pragma unroll
    for (int k = 0; k < 4; k++) {
        int ll = l - 3 + k;
        if (ll >= 0)
            s = fmaf(g_xz[(size_t)(idx - 3 + k) * 768 + d], cw[d * 4 + k], s);
    }
    float r = s / (1.f + expf(-s));
    g_uact[gid] = r;
    g_uactb[gid] = __float2bfloat16(r);
}

// ---------------- dt_proj + softplus -------------------------------------------
__global__ void dtproj_kernel(const float* __restrict__ dpw, const float* __restrict__ dpb) {
    int idx = blockIdx.x;
    int d = threadIdx.x;
    __shared__ float dts[DTR];
    if (d < DTR) dts[d] = g_dbc[idx * DBC_N + d];
    __syncthreads();
    float s = dpb[d];
#pragma unroll
    for (int r = 0; r < DTR; r++) s = fmaf(dts[r], dpw[d * DTR + r], s);
    g_delta[(size_t)idx * DI + d] = fmaxf(s, 0.f) + log1pf(expf(-fabsf(s)));
}

// ---------------- selective scan (fast ex2 chain, 2-deep prefetch) --------------
__global__ __launch_bounds__(128)
void scan_kernel(const float* __restrict__ A_log, const float* __restrict__ Dv) {
    int tid = threadIdx.x;
    int g = blockIdx.x * 8 + (tid >> 4);
    int lane = tid & 15;
    int b = g / DI, d = g - b * DI;
    float An2 = -expf(A_log[d * DS + lane]) * 1.44269504f;
    float Dd = Dv[d];
    float h = 0.f;
    int base = b * LSEQ;

    float delta = g_delta[(size_t)base * DI + d];
    float uu    = g_uact [(size_t)base * DI + d];
    float Bn    = g_dbc[base * DBC_N + DTR + lane];
    float Cn    = g_dbc[base * DBC_N + DTR + DS + lane];

    for (int l = 0; l < LSEQ; l++) {
        int idx = base + l;
        int nidx = idx + ((l < LSEQ - 1) ? 1 : 0);
        float nd = g_delta[(size_t)nidx * DI + d];
        float nu = g_uact [(size_t)nidx * DI + d];
        float nB = g_dbc[nidx * DBC_N + DTR + lane];
        float nC = g_dbc[nidx * DBC_N + DTR + DS + lane];

        h = fmaf(ex2_approx(delta * An2), h, delta * Bn * uu);
        float t = h * Cn;
        t += __shfl_xor_sync(0xffffffffu, t, 8);
        t += __shfl_xor_sync(0xffffffffu, t, 4);
        t += __shfl_xor_sync(0xffffffffu, t, 2);
        t += __shfl_xor_sync(0xffffffffu, t, 1);
        if (lane == 0) {
            float z = g_xz[(size_t)idx * 768 + DI + d];
            float y = fmaf(uu, Dd, t);
            g_ygb[(size_t)idx * DI + d] = __float2bfloat16(y * (z / (1.f + expf(-z))));
        }
        delta = nd; uu = nu; Bn = nB; Cn = nC;
    }
}

// ---------------- WMMA bf16 deconv: cp.async double-buffered K-pipeline ---------
#define KC 64
#define BST 72
#define BUFB (128 * BST * 2)
#define SSTRIDE 132
__global__ __launch_bounds__(256, 2)
void deconv_wmma_kernel(const bf16* __restrict__ G, const bf16* __restrict__ Wt,
                        const float* __restrict__ bias, bf16* __restrict__ out)
{
    extern __shared__ char smem[];
    float* stage = (float*)smem;
    uint32_t sa[2] = { smem_u32(smem),             smem_u32(smem + BUFB) };
    uint32_t sb[2] = { smem_u32(smem + 2 * BUFB),  smem_u32(smem + 3 * BUFB) };

    int tid = threadIdx.x;
    int bn = blockIdx.x * 128, bm = blockIdx.y * 128;
    float bv = bias[bn >> 8];

    const bf16* gsrc = G + (size_t)bm * DM;
    const bf16* wsrc = Wt + (size_t)bn * DM;

    int fr = tid >> 3, fj = (tid & 7) * 8;
    auto fill = [&](int buf, int c) {
        int koff = c * KC + fj;
#pragma unroll
        for (int rr = 0; rr < 128; rr += 32) {
            int r = fr + rr;
            uint32_t da = sa[buf] + (uint32_t)(r * BST + fj) * 2;
            uint32_t db = sb[buf] + (uint32_t)(r * BST + fj) * 2;
            asm volatile("cp.async.cg.shared.global [%0], [%1], 16;"
                         :: "r"(da), "l"(gsrc + (size_t)r * DM + koff));
            asm volatile("cp.async.cg.shared.global [%0], [%1], 16;"
                         :: "r"(db), "l"(wsrc + (size_t)r * DM + koff));
        }
        asm volatile("cp.async.commit_group;");
    };

    int wid = tid >> 5;
    int wm = (wid >> 2) * 64;
    int wn = (wid & 3) * 32;

    wmma::fragment<wmma::accumulator, 16, 16, 16, float> acc[4][2];
#pragma unroll
    for (int i = 0; i < 4; i++)
#pragma unroll
        for (int j = 0; j < 2; j++) wmma::fill_fragment(acc[i][j], 0.f);

    const bf16* Ab[2] = { (const bf16*)smem, (const bf16*)(smem + BUFB) };
    const bf16* Bb[2] = { (const bf16*)(smem + 2 * BUFB), (const bf16*)(smem + 3 * BUFB) };
    auto compute = [&](int buf) {
#pragma unroll
        for (int kk = 0; kk < KC; kk += 16) {
            wmma::fragment<wmma::matrix_b, 16, 16, 16, bf16, wmma::col_major> bf_[2];
#pragma unroll
            for (int j = 0; j < 2; j++)
                wmma::load_matrix_sync(bf_[j], Bb[buf] + (wn + j * 16) * BST + kk, BST);
#pragma unroll
            for (int i = 0; i < 4; i++) {
                wmma::fragment<wmma::matrix_a, 16, 16, 16, bf16, wmma::row_major> afi;
                wmma::load_matrix_sync(afi, Ab[buf] + (wm + i * 16) * BST + kk, BST);
                wmma::mma_sync(acc[i][0], afi, bf_[0], acc[i][0]);
                wmma::mma_sync(acc[i][1], afi, bf_[1], acc[i][1]);
            }
        }
    };

    fill(0, 0);
    fill(1, 1);
    asm volatile("cp.async.wait_group 1;");
    __syncthreads();
    compute(0);
    __syncthreads();
    fill(0, 2);
    asm volatile("cp.async.wait_group 1;");
    __syncthreads();
    compute(1);
    __syncthreads();
    asm volatile("cp.async.wait_group 0;");
    __syncthreads();
    compute(0);

#pragma unroll
    for (int i = 0; i < 4; i++)
#pragma unroll
        for (int j = 0; j < 2; j++)
#pragma unroll
            for (int t = 0; t < acc[i][j].num_elements; t++)
                acc[i][j].x[t] = fmaxf(acc[i][j].x[t] + bv, 0.f);

    __syncthreads();
#pragma unroll
    for (int i = 0; i < 4; i++)
#pragma unroll
        for (int j = 0; j < 2; j++)
            wmma::store_matrix_sync(stage + (wm + i * 16) * SSTRIDE + wn + j * 16,
                                    acc[i][j], SSTRIDE, wmma::mem_row_major);
    __syncthreads();

    {
        int b_img  = bm >> 10;
        int h_base = (bm & 1023) >> 5;
        int dch    = bn >> 8;
        int p_base = (bn >> 4) & 15;
        bf16* dst = out + (size_t)b_img * 16777216 + (size_t)dch * 262144;
#pragma unroll 8
        for (int i = tid; i < 2048; i += 256) {
            int row = i >> 6;
            int c8  = (i & 63) * 8;
            int h = row >> 3, p = row & 7;
            int w = c8 >> 4, q = c8 & 15;
            const float* sp = stage + (h * 32 + w) * SSTRIDE + p * 16 + q;
            float4 v0 = *(const float4*)sp;
            float4 v1 = *(const float4*)(sp + 4);
            __nv_bfloat162 o0 = __floats2bfloat162_rn(v0.x, v0.y);
            __nv_bfloat162 o1 = __floats2bfloat162_rn(v0.z, v0.w);
            __nv_bfloat162 o2 = __floats2bfloat162_rn(v1.x, v1.y);
            __nv_bfloat162 o3 = __floats2bfloat162_rn(v1.z, v1.w);
            uint4 pkv;
            pkv.x = *(uint32_t*)&o0; pkv.y = *(uint32_t*)&o1;
            pkv.z = *(uint32_t*)&o2; pkv.w = *(uint32_t*)&o3;
            *(uint4*)(dst + (size_t)((h_base + h) * 16 + p_base + p) * 512 + c8) = pkv;
        }
    }
}

// ---------------- 3x3 conv + sigmoid: R9 geometry + conflict-free LDS.128 -------
// 64-wide x 16-high tiles, 8-channel chunks, flat coalesced loader (R9 baseline);
// compute reads two aligned float4 per (ch,dy) instead of six 4-way-conflicted LDS.32
#define C3_TS 68
__global__ __launch_bounds__(256)
void conv3_sigmoid_kernel(const float* __restrict__ W, const float* __restrict__ wb,
                          float* __restrict__ out) {
    extern __shared__ char c3sm[];
    u64*   ws2  = (u64*)c3sm;                 // 1728 packed weight pairs (13824 B)
    float* tile = (float*)(c3sm + 13824);     // 8 ch x 18 rows x C3_TS

    int b = blockIdx.z, th = blockIdx.y, tw = blockIdx.x;
    int tid = threadIdx.x;
    for (int i = tid; i < 1728; i += 256) { float w = W[i]; ws2[i] = pk2(w, w); }

    int py = tid >> 4, px = tid & 15;
    int y0 = th * 16 - 1;
    int x0 = tw * 64 - 2;

    u64 accA[3], accB[3];
#pragma unroll
    for (int oc = 0; oc < 3; oc++) { accA[oc] = pk2(wb[oc], wb[oc]); accB[oc] = accA[oc]; }

    for (int c0 = 0; c0 < 64; c0 += 8) {
        __syncthreads();
        // flat loader: 8 ch x 18 rows x 34 bf16-pairs
        for (int i = tid; i < 8 * 18 * 34; i += 256) {
            int dl = i / (18 * 34), rem = i - dl * (18 * 34);
            int r = rem / 34, j = rem - r * 34;
            int yy = y0 + r, xx = x0 + j * 2;
            float2 f = make_float2(0.f, 0.f);
            if (yy >= 0 && yy < 512) {
                const bf16* src = g_decb + (((size_t)b * 64 + c0 + dl) * 512 + yy) * 512;
                if (xx >= 0 && xx + 1 < 512) {
                    __nv_bfloat162 v = *(const __nv_bfloat162*)(src + xx);
                    f.x = __bfloat162float(v.x); f.y = __bfloat162float(v.y);
                } else {
                    if (xx >= 0 && xx < 512)         f.x = __bfloat162float(src[xx]);
                    if (xx + 1 >= 0 && xx + 1 < 512) f.y = __bfloat162float(src[xx + 1]);
                }
            }
            *(float2*)(tile + (dl * 18 + r) * C3_TS + j * 2) = f;
        }
        __syncthreads();

#pragma unroll
        for (int dl = 0; dl < 8; dl++) {
            int d = c0 + dl;
            const u64* w0 = ws2 + d * 9;
            const u64* w1 = ws2 + (64 + d) * 9;
            const u64* w2 = ws2 + (128 + d) * 9;
            const float* trow = tile + dl * 18 * C3_TS + px * 4;   // 16B aligned
#pragma unroll
            for (int dy = 0; dy < 3; dy++) {
                const float* t = trow + (py + dy) * C3_TS;
                float4 a  = *(const float4*)t;        // cols px*4 .. px*4+3 (LDS.128)
                float4 bq = *(const float4*)(t + 4);  // cols px*4+4 .. px*4+7
                // needed window: cols px*4+1 .. px*4+6 = a.y..a.w, bq.x..bq.z
                u64 p01 = pk2(a.y, a.z), p12 = pk2(a.z, a.w), p23 = pk2(a.w, bq.x);
                u64 p34 = pk2(bq.x, bq.y), p45 = pk2(bq.y, bq.z);
                int wi = dy * 3;
                fma2(accA[0], p01, w0[wi]); fma2(accA[0], p12, w0[wi+1]); fma2(accA[0], p23, w0[wi+2]);
                fma2(accA[1], p01, w1[wi]); fma2(accA[1], p12, w1[wi+1]); fma2(accA[1], p23, w1[wi+2]);
                fma2(accA[2], p01, w2[wi]); fma2(accA[2], p12, w2[wi+1]); fma2(accA[2], p23, w2[wi+2]);
                fma2(accB[0], p23, w0[wi]); fma2(accB[0], p34, w0[wi+1]); fma2(accB[0], p45, w0[wi+2]);
                fma2(accB[1], p23, w1[wi]); fma2(accB[1], p34, w1[wi+1]); fma2(accB[1], p45, w1[wi+2]);
                fma2(accB[2], p23, w2[wi]); fma2(accB[2], p34, w2[wi+1]); fma2(accB[2], p45, w2[wi+2]);
            }
        }
    }

    int Y = th * 16 + py, X0 = tw * 64 + px * 4;
    size_t o = (size_t)b * 3 * 262144 + (size_t)Y * 512 + X0;
#pragma unroll
    for (int oc = 0; oc < 3; oc++) {
        float a0, a1, a2, a3;
        unpk2(a0, a1, accA[oc]);
        unpk2(a2, a3, accB[oc]);
        float* dst = out + o + (size_t)oc * 262144;
        dst[0] = 1.f / (1.f + expf(-a0));
        dst[1] = 1.f / (1.f + expf(-a1));
        dst[2] = 1.f / (1.f + expf(-a2));
        dst[3] = 1.f / (1.f + expf(-a3));
    }
}

// ---------------- launch --------------------------------------------------------
extern "C" void kernel_launch(void* const* d_in, const int* in_sizes, int n_in,
                              void* d_out, int out_size) {
    const float* x         = (const float*)d_in[0];
    const float* patch_w   = (const float*)d_in[1];
    const float* patch_b   = (const float*)d_in[2];
    const float* in_proj_w = (const float*)d_in[3];
    const float* conv1d_w  = (const float*)d_in[4];
    const float* conv1d_b  = (const float*)d_in[5];
    const float* x_proj_w  = (const float*)d_in[6];
    const float* dt_proj_w = (const float*)d_in[7];
    const float* dt_proj_b = (const float*)d_in[8];
    const float* A_log     = (const float*)d_in[9];
    const float* Dv        = (const float*)d_in[10];
    const float* out_proj_w= (const float*)d_in[11];
    const float* deconv_w  = (const float*)d_in[12];
    const float* deconv_b  = (const float*)d_in[13];
    const float* dec_conv_w= (const float*)d_in[14];
    const float* dec_conv_b= (const float*)d_in[15];
    float* out = (float*)d_out;

    bf16 *Apeb, *seqb, *uactb, *ygb, *goutb, *wtb, *decb, *pwb, *ipwb, *xpwb, *opwb;
    float *xz, *uact, *dbc, *delta;
    cudaGetSymbolAddress((void**)&Apeb, g_Apeb);
    cudaGetSymbolAddress((void**)&seqb, g_seqb);
    cudaGetSymbolAddress((void**)&xz,   g_xz);
    cudaGetSymbolAddress((void**)&uact, g_uact);
    cudaGetSymbolAddress((void**)&uactb,g_uactb);
    cudaGetSymbolAddress((void**)&dbc,  g_dbc);
    cudaGetSymbolAddress((void**)&delta,g_delta);
    cudaGetSymbolAddress((void**)&ygb,  g_ygb);
    cudaGetSymbolAddress((void**)&goutb,g_goutb);
    cudaGetSymbolAddress((void**)&wtb,  g_wtb);
    cudaGetSymbolAddress((void**)&decb, g_decb);
    cudaGetSymbolAddress((void**)&pwb,  g_pwb);
    cudaGetSymbolAddress((void**)&ipwb, g_ipwb);
    cudaGetSymbolAddress((void**)&xpwb, g_xpwb);
    cudaGetSymbolAddress((void**)&opwb, g_opwb);

    const int DSMEM = 4 * BUFB;                              // 73728
    const int C3SMEM = 13824 + 8 * 18 * C3_TS * 4;           // 52992
    cudaFuncSetAttribute(deconv_wmma_kernel,
                         cudaFuncAttributeMaxDynamicSharedMemorySize, DSMEM);
    cudaFuncSetAttribute(conv3_sigmoid_kernel,
                         cudaFuncAttributeMaxDynamicSharedMemorySize, C3SMEM);

    im2col_kernel<<<(ROWS * 768 + 255) / 256, 256>>>(x);
    cvt_weights_kernel<<<(W3 + 255)/256, 256>>>(patch_w, in_proj_w, x_proj_w, out_proj_w);
    transpose_w_kernel<<<dim3(NDEC / 32, 6), 256>>>(deconv_w);

    wgemm_kernel<true><<<dim3(3, 64), 256>>>(Apeb, pwb, patch_b, seqb, DM, 768);
    wgemm_kernel<false><<<dim3(12, 64), 256>>>(seqb, ipwb, nullptr, xz, 2 * DI, DM);
    conv1d_silu_kernel<<<(ROWS * DI + 255) / 256, 256>>>(conv1d_w, conv1d_b);
    wgemm_kernel<false><<<dim3(1, 64), 256>>>(uactb, xpwb, nullptr, dbc, DBC_N, DI);
    dtproj_kernel<<<ROWS, DI>>>(dt_proj_w, dt_proj_b);
    scan_kernel<<<384, 128>>>(A_log, Dv);
    wgemm_kernel<true><<<dim3(3, 64), 256>>>(ygb, opwb, nullptr, goutb, DM, DI);
    deconv_wmma_kernel<<<dim3(128, 64), 256, DSMEM>>>(goutb, wtb, deconv_b, decb);
    conv3_sigmoid_kernel<<<dim3(8, 32, 8), 256, C3SMEM>>>(dec_conv_w, dec_conv_b, out);
}